// round 7
// baseline (speedup 1.0000x reference)
#include <cuda_runtime.h>
#include <math_constants.h>

// Problem constants
#define NB 32
#define NP 576
#define ND 768
#define KP1 17
#define KF 16
#define NC 200
#define NDV 192       // ulonglong2 (16B) per 768-float row
#define TILE 32       // patches per k1 block

// Output layout: concatenation of (A, v_norm, logits_parts, logits_agg)
#define SZ_A (NB*KP1*NP)            // 313344
#define OFF_VN (SZ_A)
#define SZ_VN (NB*KF*ND)            // 393216
#define OFF_PARTS (OFF_VN + SZ_VN)
#define SZ_PARTS (NB*KF*NC)         // 102400
#define OFF_AGG (OFF_PARTS + SZ_PARTS)

typedef unsigned long long u64;

// v accumulator (pre-LN). Zeroed at module load; k2a re-zeroes after reading,
// so the "g_v == 0 on k1 entry" invariant holds across graph replays.
__device__ float g_v[NB*KF*ND];
// classifier partials: [dc 16][b 32][k 16][c 200], fully rewritten each launch
__device__ float g_lp[16*NB*KF*NC];

// ---- f32x2 packed-FMA helpers ----------------------------------------------
__device__ __forceinline__ u64 fma2(u64 a, u64 b, u64 c) {
    u64 d; asm("fma.rn.f32x2 %0, %1, %2, %3;" : "=l"(d) : "l"(a), "l"(b), "l"(c));
    return d;
}
__device__ __forceinline__ u64 pack2(float lo, float hi) {
    u64 r; asm("mov.b64 %0, {%1,%2};" : "=l"(r) : "f"(lo), "f"(hi));
    return r;
}
__device__ __forceinline__ float2 unpack2(u64 v) {
    float2 r; asm("mov.b64 {%0,%1}, %2;" : "=f"(r.x), "=f"(r.y) : "l"(v));
    return r;
}

// ---------------------------------------------------------------------------
// k1 phase-1 helper: 2 patches per warp, prototypes [K0, K0+KN).
// x and proto both read via LDG (L1/L2-resident). acc = 2*KN u64 regs.
// Reduction: 3 shfl levels -> 4 partials stored by lanes 0-3.
// ---------------------------------------------------------------------------
template<int K0, int KN>
__device__ __forceinline__ void dot_pass2(const ulonglong2* __restrict__ xr2, int p0,
                                          const ulonglong2* __restrict__ pr2,
                                          float* a_part, int lane)
{
    u64 acc0[KN], acc1[KN];
    #pragma unroll
    for (int k = 0; k < KN; k++) { acc0[k] = 0ULL; acc1[k] = 0ULL; }

    #pragma unroll
    for (int j = 0; j < 6; j++) {
        ulonglong2 xv0 = __ldg(&xr2[(size_t)p0*NDV + j*32 + lane]);
        ulonglong2 xv1 = __ldg(&xr2[(size_t)(p0+1)*NDV + j*32 + lane]);
        #pragma unroll
        for (int k = 0; k < KN; k++) {
            ulonglong2 pv = __ldg(&pr2[(K0 + k)*NDV + j*32 + lane]);
            acc0[k] = fma2(xv0.x, pv.x, acc0[k]);
            acc0[k] = fma2(xv0.y, pv.y, acc0[k]);
            acc1[k] = fma2(xv1.x, pv.x, acc1[k]);
            acc1[k] = fma2(xv1.y, pv.y, acc1[k]);
        }
    }
    #pragma unroll
    for (int k = 0; k < KN; k++) {
        float2 h0 = unpack2(acc0[k]);
        float v0 = h0.x + h0.y;
        v0 += __shfl_xor_sync(0xffffffffu, v0, 16);
        v0 += __shfl_xor_sync(0xffffffffu, v0, 8);
        v0 += __shfl_xor_sync(0xffffffffu, v0, 4);
        float2 h1 = unpack2(acc1[k]);
        float v1 = h1.x + h1.y;
        v1 += __shfl_xor_sync(0xffffffffu, v1, 16);
        v1 += __shfl_xor_sync(0xffffffffu, v1, 8);
        v1 += __shfl_xor_sync(0xffffffffu, v1, 4);
        if (lane < 4) {
            a_part[(size_t)p0*(KP1*4)     + (K0 + k)*4 + lane] = v0;
            a_part[(size_t)(p0+1)*(KP1*4) + (K0 + k)*4 + lane] = v1;
        }
    }
}

// ---------------------------------------------------------------------------
// k1: per (tile of 32 patches, image) block. 256 threads, 13 KB smem,
// launch_bounds(256,4) -> 32 warps/SM. x is NOT staged; L1/L2 carries it.
//  Phase 1: 2 sweeps x (2 patches/warp), 2 k-passes each -> softmax.
//  Phase 2: 192 threads own d-quads, 2 k-halves; float4 atomics only.
// ---------------------------------------------------------------------------
__global__ __launch_bounds__(256, 4)
void k1(const float* __restrict__ x,
        const float* __restrict__ proto,
        float* __restrict__ out)
{
    __shared__ float a_part[TILE*KP1*4];            // 8.5 KB
    __shared__ float a_s[TILE*KP1];                 // raw a (A writer)
    __shared__ __align__(16) float a_c[TILE*KF];    // compact a (phase 2)
    __shared__ float psq[KP1];

    const int t = threadIdx.x, warp = t >> 5, lane = t & 31;
    const int tile = blockIdx.x, b = blockIdx.y;
    const float* xb = x + ((size_t)b*NP + (size_t)tile*TILE)*ND;
    const ulonglong2* xr2 = (const ulonglong2*)xb;
    const ulonglong2* pr2 = (const ulonglong2*)proto;

    // ||p_k||^2 per block (proto is L2/L1-resident)
    for (int k = warp; k < KP1; k += 8) {
        const float4* pk = (const float4*)(proto + (size_t)k*ND);
        float s = 0.f;
        #pragma unroll
        for (int i = 0; i < 6; i++) {
            float4 v = __ldg(&pk[lane + 32*i]);
            s += v.x*v.x + v.y*v.y + v.z*v.z + v.w*v.w;
        }
        #pragma unroll
        for (int o = 16; o; o >>= 1) s += __shfl_xor_sync(0xffffffffu, s, o);
        if (lane == 0) psq[k] = s;
    }
    __syncthreads();

    // --- Phase 1: 2 sweeps of 16 patches (2 per warp) ---
    #pragma unroll 1
    for (int sweep = 0; sweep < 2; sweep++) {
        const int p0 = sweep*16 + warp*2;
        dot_pass2<0, 9>(xr2, p0, pr2, a_part, lane);
        dot_pass2<9, 8>(xr2, p0, pr2, a_part, lane);
        __syncwarp();

        // lane-parallel softmax: softmax_k(2*xp - psq) == softmax(-dists)
        const float4* a_part4 = (const float4*)a_part;
        #pragma unroll
        for (int pp = 0; pp < 2; pp++) {
            const int pl = p0 + pp;
            float s = -CUDART_INF_F;
            if (lane < KP1) {
                float4 t4 = a_part4[pl*KP1 + lane];
                float dot = (t4.x + t4.y) + (t4.z + t4.w);
                s = fmaf(2.f, dot, -psq[lane]);
            }
            float m = s;
            #pragma unroll
            for (int o = 16; o; o >>= 1) m = fmaxf(m, __shfl_xor_sync(0xffffffffu, m, o));
            float e = (lane < KP1) ? __expf(s - m) : 0.f;
            float ssum = e;
            #pragma unroll
            for (int o = 16; o; o >>= 1) ssum += __shfl_xor_sync(0xffffffffu, ssum, o);
            float av = e * (1.f / ssum);
            if (lane < KP1) {
                a_s[pl*KP1 + lane] = av;
                if (lane < KF) a_c[pl*KF + lane] = av;
            }
        }
    }
    __syncthreads();

    if (t >= 192) {
        // --- A output on otherwise-idle threads ---
        int tt = t - 192;
        #pragma unroll
        for (int i = tt; i < KP1*TILE; i += 64) {
            int k = i >> 5, p = i & 31;
            out[((size_t)b*KP1 + k)*NP + (size_t)tile*TILE + p] = a_s[p*KP1 + k];
        }
    } else {
        // --- Phase 2: thread owns d-quad 4t..4t+3; two k-halves ---
        const float4* xg4 = (const float4*)xb;     // row stride NDV float4
        float* gv = g_v + (size_t)b*KF*ND;
        #pragma unroll 1
        for (int half = 0; half < 2; half++) {
            u64 vacc[4][4];
            #pragma unroll
            for (int kp = 0; kp < 4; kp++)
                #pragma unroll
                for (int d = 0; d < 4; d++) vacc[kp][d] = 0ULL;

            #pragma unroll 4
            for (int p = 0; p < TILE; p++) {
                float4 xv = __ldg(&xg4[(size_t)p*NDV + t]);
                u64 xd[4] = { pack2(xv.x, xv.x), pack2(xv.y, xv.y),
                              pack2(xv.z, xv.z), pack2(xv.w, xv.w) };
                const ulonglong2* a2 = (const ulonglong2*)(a_c + p*KF + half*8);
                ulonglong2 A0 = a2[0], A1 = a2[1];
                u64 ap[4] = { A0.x, A0.y, A1.x, A1.y };
                #pragma unroll
                for (int kp = 0; kp < 4; kp++)
                    #pragma unroll
                    for (int d = 0; d < 4; d++)
                        vacc[kp][d] = fma2(ap[kp], xd[d], vacc[kp][d]);
            }
            #pragma unroll
            for (int kp = 0; kp < 4; kp++) {
                int k0 = half*8 + 2*kp;
                float2 h0 = unpack2(vacc[kp][0]), h1 = unpack2(vacc[kp][1]);
                float2 h2 = unpack2(vacc[kp][2]), h3 = unpack2(vacc[kp][3]);
                atomicAdd((float4*)&gv[(size_t)k0*ND + 4*t],
                          make_float4(h0.x, h1.x, h2.x, h3.x));
                atomicAdd((float4*)&gv[(size_t)(k0+1)*ND + 4*t],
                          make_float4(h0.y, h1.y, h2.y, h3.y));
            }
        }
    }
}

// ---------------------------------------------------------------------------
// k2a: LayerNorm over D for each (b,k). Applies the /P scaling.
// Re-zeroes g_v after reading (invariant for next graph replay).
// ---------------------------------------------------------------------------
__global__ __launch_bounds__(256, 4)
void k2a(float* __restrict__ out,
         const float* __restrict__ gamma, const float* __restrict__ beta)
{
    const int bk = blockIdx.x;            // b*16 + k
    const int t = threadIdx.x;
    __shared__ float red[16];
    __shared__ float stats[2];
    float* gv = g_v + (size_t)bk*ND;
    const float invP = 1.f / (float)NP;

    float v[3]; float s = 0.f, sq = 0.f;
    #pragma unroll
    for (int i = 0; i < 3; i++) {
        float val = gv[t + i*256] * invP;
        gv[t + i*256] = 0.f;              // re-zero for next replay's k1
        v[i] = val; s += val; sq += val*val;
    }
    #pragma unroll
    for (int o = 16; o; o >>= 1) {
        s  += __shfl_xor_sync(0xffffffffu, s, o);
        sq += __shfl_xor_sync(0xffffffffu, sq, o);
    }
    if ((t & 31) == 0) { red[t >> 5] = s; red[8 + (t >> 5)] = sq; }
    __syncthreads();
    if (t == 0) {
        float S = 0.f, Q = 0.f;
        #pragma unroll
        for (int w = 0; w < 8; w++) { S += red[w]; Q += red[8 + w]; }
        float mu  = S * (1.f/ND);
        float var = Q * (1.f/ND) - mu*mu;
        stats[0] = mu; stats[1] = rsqrtf(var + 1e-6f);
    }
    __syncthreads();
    const float mu = stats[0], rs = stats[1];
    #pragma unroll
    for (int i = 0; i < 3; i++) {
        int d = t + i*256;
        out[OFF_VN + (size_t)bk*ND + d] = (v[i] - mu) * rs * gamma[d] + beta[d];
    }
}

// ---------------------------------------------------------------------------
// k2b: per (dc, b): partial logits over a 48-d chunk -> g_lp (plain stores,
// NO atomics). 512 blocks, w L2-resident, f32x2 inner product.
// ---------------------------------------------------------------------------
#define DCH 48
__global__ __launch_bounds__(256, 4)
void k2b(const float* __restrict__ w, const float* __restrict__ out_ro)
{
    const int dc = blockIdx.x;            // 0..15
    const int b  = blockIdx.y;
    const int t  = threadIdx.x;
    __shared__ u64 vn_s[KF*(DCH/2)];      // packed vn d-pairs (3 KB)

    const float* vn = out_ro + OFF_VN + (size_t)b*KF*ND + dc*DCH;
    for (int i = t; i < KF*(DCH/2); i += 256) {
        int k = i / (DCH/2), dp = i - k*(DCH/2);
        float2 v = *(const float2*)&vn[(size_t)k*ND + 2*dp];
        vn_s[i] = pack2(v.x, v.y);
    }
    __syncthreads();

    if (t < NC) {
        const float* wp = w + (size_t)(dc*DCH)*NC + t;   // coalesced in c
        u64 acc[KF];
        #pragma unroll
        for (int k = 0; k < KF; k++) acc[k] = 0ULL;
        #pragma unroll 8
        for (int dp = 0; dp < DCH/2; dp++) {
            float w0 = __ldg(wp + (size_t)(2*dp)*NC);
            float w1 = __ldg(wp + (size_t)(2*dp + 1)*NC);
            u64 wv = pack2(w0, w1);
            #pragma unroll
            for (int k = 0; k < KF; k++)
                acc[k] = fma2(vn_s[k*(DCH/2) + dp], wv, acc[k]);
        }
        float* lp = g_lp + (((size_t)dc*NB + b)*KF)*NC + t;
        #pragma unroll
        for (int k = 0; k < KF; k++) {
            float2 h = unpack2(acc[k]);
            lp[(size_t)k*NC] = h.x + h.y;            // plain STG, coalesced
        }
    }
}

// ---------------------------------------------------------------------------
// k2c: reduce the 16 dc-partials + bias -> logits_parts; fold k-mean -> agg.
// 32 blocks; 256 fully-independent loads per thread (huge MLP).
// ---------------------------------------------------------------------------
__global__ __launch_bounds__(256, 8)
void k2c(const float* __restrict__ b_cls, float* __restrict__ out)
{
    const int b = blockIdx.x, t = threadIdx.x;
    if (t >= NC) return;
    const float bias = __ldg(&b_cls[t]);
    float agg = 0.f;
    #pragma unroll
    for (int k = 0; k < KF; k++) {
        float s = bias;
        #pragma unroll
        for (int dc = 0; dc < 16; dc++)
            s += g_lp[(((size_t)dc*NB + b)*KF + k)*NC + t];
        out[OFF_PARTS + ((size_t)b*KF + k)*NC + t] = s;
        agg += s;
    }
    out[OFF_AGG + (size_t)b*NC + t] = agg * (1.f/KF);
}

// ---------------------------------------------------------------------------
extern "C" void kernel_launch(void* const* d_in, const int* in_sizes, int n_in,
                              void* d_out, int out_size)
{
    const float* x     = (const float*)d_in[0];  // (32,24,24,768)
    const float* proto = (const float*)d_in[1];  // (17,768)
    const float* gamma = (const float*)d_in[2];  // (768,)
    const float* beta  = (const float*)d_in[3];  // (768,)
    const float* w     = (const float*)d_in[4];  // (768,200)
    const float* bc    = (const float*)d_in[5];  // (200,)
    float* out = (float*)d_out;

    k1<<<dim3(18, NB), 256>>>(x, proto, out);
    k2a<<<NB*KF, 256>>>(out, gamma, beta);
    k2b<<<dim3(16, NB), 256>>>(w, out);
    k2c<<<NB, 256>>>(bc, out);
}

// round 8
// speedup vs baseline: 1.0420x; 1.0420x over previous
#include <cuda_runtime.h>
#include <math_constants.h>

// Problem constants
#define NB 32
#define NP 576
#define ND 768
#define KP1 17
#define KF 16
#define NC 200
#define TILE_P 24
#define NTILES 24     // 576 / 24
#define T1 256
#define NDV 192       // 16B units (ulonglong2 / float4) per 768-float row

// Output layout: concatenation of (A, v_norm, logits_parts, logits_agg)
#define SZ_A (NB*KP1*NP)            // 313344
#define OFF_VN (SZ_A)
#define SZ_VN (NB*KF*ND)            // 393216
#define OFF_PARTS (OFF_VN + SZ_VN)
#define SZ_PARTS (NB*KF*NC)         // 102400
#define OFF_AGG (OFF_PARTS + SZ_PARTS)

typedef unsigned long long u64;

// v accumulator (pre-LN). Zeroed at module load; k2a re-zeroes after reading,
// so the "g_v == 0 on k1 entry" invariant holds across graph replays.
__device__ float g_v[NB*KF*ND];

// ---- f32x2 packed-FMA helpers ----------------------------------------------
__device__ __forceinline__ u64 fma2(u64 a, u64 b, u64 c) {
    u64 d; asm("fma.rn.f32x2 %0, %1, %2, %3;" : "=l"(d) : "l"(a), "l"(b), "l"(c));
    return d;
}
__device__ __forceinline__ u64 pack2(float lo, float hi) {
    u64 r; asm("mov.b64 %0, {%1,%2};" : "=l"(r) : "f"(lo), "f"(hi));
    return r;
}
__device__ __forceinline__ float2 unpack2(u64 v) {
    float2 r; asm("mov.b64 {%0,%1}, %2;" : "=f"(r.x), "=f"(r.y) : "l"(v));
    return r;
}

// ---------------------------------------------------------------------------
// k1 phase-1 helper: 3 patches per warp, prototypes [K0, K0+KN).
// Full shfl reduce; lane (K0+k) captures dot k into its private register
// sk[p] — no scratch smem needed for the reduction at all.
// ---------------------------------------------------------------------------
template<int K0, int KN>
__device__ __forceinline__ void dot_pass3(const ulonglong2* __restrict__ xs2,
                                          const float* __restrict__ proto,
                                          int p0, int lane, float sk[3])
{
    u64 acc[3][KN];
    #pragma unroll
    for (int p = 0; p < 3; p++)
        #pragma unroll
        for (int k = 0; k < KN; k++) acc[p][k] = 0ULL;

    const ulonglong2* pr2 = (const ulonglong2*)proto;
    #pragma unroll
    for (int j = 0; j < 6; j++) {
        ulonglong2 xv[3];
        #pragma unroll
        for (int p = 0; p < 3; p++) xv[p] = xs2[(p0 + p)*NDV + j*32 + lane];
        #pragma unroll
        for (int k = 0; k < KN; k++) {
            ulonglong2 pv = __ldg(&pr2[(K0 + k)*NDV + j*32 + lane]);
            #pragma unroll
            for (int p = 0; p < 3; p++) {
                acc[p][k] = fma2(xv[p].x, pv.x, acc[p][k]);
                acc[p][k] = fma2(xv[p].y, pv.y, acc[p][k]);
            }
        }
    }
    #pragma unroll
    for (int p = 0; p < 3; p++)
        #pragma unroll
        for (int k = 0; k < KN; k++) {
            float2 h = unpack2(acc[p][k]);
            float v = h.x + h.y;
            #pragma unroll
            for (int o = 16; o; o >>= 1) v += __shfl_xor_sync(0xffffffffu, v, o);
            if (lane == K0 + k) sk[p] = v;   // lane-select: lane k owns dot k
        }
}

// ---------------------------------------------------------------------------
// k1: per (24-patch tile, image) block. 256 threads, 75.4 KB smem,
// launch_bounds(256,3) -> target 3 blocks/SM (24 warps).
//  Phase 1: smem x-tile, 3 patches/warp, k-split 2, lane-resident softmax.
//  Phase 2: 192 threads own d-quads, two k-halves; float4 atomics only.
// ---------------------------------------------------------------------------
__global__ __launch_bounds__(T1, 3)
void k1(const float* __restrict__ x,
        const float* __restrict__ proto,
        float* __restrict__ out)
{
    extern __shared__ float sm[];
    float* xs  = sm;                       // 24*768 floats (73.7 KB)
    float* a_c = xs + TILE_P*ND;           // 24*16 compact a (16B-aligned)
    float* a16 = a_c + TILE_P*KF;          // 24 (k=16 attention)
    float* psq = a16 + TILE_P;             // 17

    const int t = threadIdx.x, warp = t >> 5, lane = t & 31;
    const int tile = blockIdx.x, b = blockIdx.y;

    // --- stage x tile (float4, coalesced): 24*192 = 4608 float4 ---
    float4* xs4 = (float4*)xs;
    const float4* xg = (const float4*)(x + ((size_t)b*NP + (size_t)tile*TILE_P)*ND);
    #pragma unroll
    for (int i = 0; i < 18; i++)
        xs4[t + i*T1] = xg[t + i*T1];

    // --- per-block ||p_k||^2 (proto L1/L2-resident, overlaps staging) ---
    for (int k = warp; k < KP1; k += 8) {
        const float4* pk = (const float4*)(proto + (size_t)k*ND);
        float s = 0.f;
        #pragma unroll
        for (int i = 0; i < 6; i++) {
            float4 v = __ldg(&pk[lane + 32*i]);
            s += v.x*v.x + v.y*v.y + v.z*v.z + v.w*v.w;
        }
        #pragma unroll
        for (int o = 16; o; o >>= 1) s += __shfl_xor_sync(0xffffffffu, s, o);
        if (lane == 0) psq[k] = s;
    }
    __syncthreads();

    // --- Phase 1: dots (k-split 9+8), softmax args land per-lane ---
    const ulonglong2* xs2 = (const ulonglong2*)xs;
    const int p0 = warp * 3;
    float sk[3];
    dot_pass3<0, 9>(xs2, proto, p0, lane, sk);
    dot_pass3<9, 8>(xs2, proto, p0, lane, sk);

    // --- lane-parallel softmax: softmax_k(2*xp - psq) == softmax(-dists) ---
    #pragma unroll
    for (int p = 0; p < 3; p++) {
        const int pl = p0 + p;
        float s = (lane < KP1) ? fmaf(2.f, sk[p], -psq[lane]) : -CUDART_INF_F;
        float m = s;
        #pragma unroll
        for (int o = 16; o; o >>= 1) m = fmaxf(m, __shfl_xor_sync(0xffffffffu, m, o));
        float e = (lane < KP1) ? __expf(s - m) : 0.f;
        float ssum = e;
        #pragma unroll
        for (int o = 16; o; o >>= 1) ssum += __shfl_xor_sync(0xffffffffu, ssum, o);
        float av = e * (1.f / ssum);
        if (lane < KF)       a_c[pl*KF + lane] = av;
        else if (lane == KF) a16[pl] = av;
    }
    __syncthreads();

    if (t >= 192) {
        // --- A output on otherwise-idle threads: rows contiguous in p ---
        int tt = t - 192;
        for (int i = tt; i < KP1*TILE_P; i += 64) {
            int k = i / TILE_P, p = i - k*TILE_P;
            float av = (k < KF) ? a_c[p*KF + k] : a16[p];
            out[((size_t)b*KP1 + k)*NP + (size_t)tile*TILE_P + p] = av;
        }
    } else {
        // --- Phase 2: thread owns d-quad 4t..4t+3; two k-halves ---
        float* gv = g_v + (size_t)b*KF*ND;
        #pragma unroll 1
        for (int half = 0; half < 2; half++) {
            u64 vacc[4][4];
            #pragma unroll
            for (int kp = 0; kp < 4; kp++)
                #pragma unroll
                for (int d = 0; d < 4; d++) vacc[kp][d] = 0ULL;

            #pragma unroll 4
            for (int p = 0; p < TILE_P; p++) {
                float4 xv = xs4[p*NDV + t];
                u64 xd[4] = { pack2(xv.x, xv.x), pack2(xv.y, xv.y),
                              pack2(xv.z, xv.z), pack2(xv.w, xv.w) };
                const ulonglong2* a2 = (const ulonglong2*)(a_c + p*KF + half*8);
                ulonglong2 A0 = a2[0], A1 = a2[1];
                u64 ap[4] = { A0.x, A0.y, A1.x, A1.y };
                #pragma unroll
                for (int kp = 0; kp < 4; kp++)
                    #pragma unroll
                    for (int d = 0; d < 4; d++)
                        vacc[kp][d] = fma2(ap[kp], xd[d], vacc[kp][d]);
            }
            #pragma unroll
            for (int kp = 0; kp < 4; kp++) {
                int k0 = half*8 + 2*kp;
                float2 h0 = unpack2(vacc[kp][0]), h1 = unpack2(vacc[kp][1]);
                float2 h2 = unpack2(vacc[kp][2]), h3 = unpack2(vacc[kp][3]);
                atomicAdd((float4*)&gv[(size_t)k0*ND + 4*t],
                          make_float4(h0.x, h1.x, h2.x, h3.x));
                atomicAdd((float4*)&gv[(size_t)(k0+1)*ND + 4*t],
                          make_float4(h0.y, h1.y, h2.y, h3.y));
            }
        }
    }
}

// ---------------------------------------------------------------------------
// k2a: LayerNorm over D for each (b,k). Applies the /P scaling.
// Re-zeroes g_v (read-then-clear) and seeds parts/agg with the bias so k2b
// can use pure red.global.add.
// ---------------------------------------------------------------------------
__global__ __launch_bounds__(256, 4)
void k2a(float* __restrict__ out,
         const float* __restrict__ gamma, const float* __restrict__ beta,
         const float* __restrict__ b_cls)
{
    const int bk = blockIdx.x;            // b*16 + k
    const int t = threadIdx.x;
    __shared__ float red[16];
    __shared__ float stats[2];
    float* gv = g_v + (size_t)bk*ND;
    const float invP = 1.f / (float)NP;

    float v[3]; float s = 0.f, sq = 0.f;
    #pragma unroll
    for (int i = 0; i < 3; i++) {
        float val = gv[t + i*256] * invP;
        gv[t + i*256] = 0.f;              // re-zero for next replay's k1
        v[i] = val; s += val; sq += val*val;
    }

    // seed logits_parts / logits_agg with the classifier bias
    if (t < NC) {
        float bcv = b_cls[t];
        out[OFF_PARTS + (size_t)bk*NC + t] = bcv;
        if ((bk & 15) == 0) out[OFF_AGG + (size_t)(bk >> 4)*NC + t] = bcv;
    }

    #pragma unroll
    for (int o = 16; o; o >>= 1) {
        s  += __shfl_xor_sync(0xffffffffu, s, o);
        sq += __shfl_xor_sync(0xffffffffu, sq, o);
    }
    if ((t & 31) == 0) { red[t >> 5] = s; red[8 + (t >> 5)] = sq; }
    __syncthreads();
    if (t == 0) {
        float S = 0.f, Q = 0.f;
        #pragma unroll
        for (int w = 0; w < 8; w++) { S += red[w]; Q += red[8 + w]; }
        float mu  = S * (1.f/ND);
        float var = Q * (1.f/ND) - mu*mu;
        stats[0] = mu; stats[1] = rsqrtf(var + 1e-6f);
    }
    __syncthreads();
    const float mu = stats[0], rs = stats[1];
    #pragma unroll
    for (int i = 0; i < 3; i++) {
        int d = t + i*256;
        out[OFF_VN + (size_t)bk*ND + d] = (v[i] - mu) * rs * gamma[d] + beta[d];
    }
}

// ---------------------------------------------------------------------------
// k2b: logits_parts[b,k,c] += vn[b,k,dchunk] @ w[dchunk,c]; agg folded in.
// 16 d-chunks of 48 per image -> 512 blocks; w L2-resident.
// Bias pre-seeded by k2a, so pure red.global.add.
// ---------------------------------------------------------------------------
#define DCH 48
__global__ __launch_bounds__(256, 4)
void k2b(const float* __restrict__ w, float* __restrict__ out)
{
    const int dc = blockIdx.x;            // 0..15
    const int b  = blockIdx.y;
    const int t  = threadIdx.x;
    __shared__ u64 vn_s[KF*(DCH/2)];      // packed d-pairs (3 KB)

    const float* vn = out + OFF_VN + (size_t)b*KF*ND + dc*DCH;
    for (int i = t; i < KF*(DCH/2); i += 256) {
        int k = i / (DCH/2), dp = i - k*(DCH/2);
        float2 v = *(const float2*)&vn[(size_t)k*ND + 2*dp];
        vn_s[i] = pack2(v.x, v.y);
    }
    __syncthreads();

    if (t < NC) {
        const float* wp = w + (size_t)(dc*DCH)*NC + t;   // coalesced in c
        u64 acc[KF];
        #pragma unroll
        for (int k = 0; k < KF; k++) acc[k] = 0ULL;
        #pragma unroll 8
        for (int dp = 0; dp < DCH/2; dp++) {
            float w0 = __ldg(wp + (size_t)(2*dp)*NC);
            float w1 = __ldg(wp + (size_t)(2*dp + 1)*NC);
            u64 wv = pack2(w0, w1);
            #pragma unroll
            for (int k = 0; k < KF; k++)
                acc[k] = fma2(vn_s[k*(DCH/2) + dp], wv, acc[k]);
        }
        float* parts = out + OFF_PARTS + (size_t)b*KF*NC + t;
        float ssum = 0.f;
        #pragma unroll
        for (int k = 0; k < KF; k++) {
            float2 h = unpack2(acc[k]);
            float s = h.x + h.y;
            atomicAdd(parts + (size_t)k*NC, s);
            ssum += s;
        }
        atomicAdd(out + OFF_AGG + b*NC + t, ssum * (1.f/KF));
    }
}

// ---------------------------------------------------------------------------
extern "C" void kernel_launch(void* const* d_in, const int* in_sizes, int n_in,
                              void* d_out, int out_size)
{
    const float* x     = (const float*)d_in[0];  // (32,24,24,768)
    const float* proto = (const float*)d_in[1];  // (17,768)
    const float* gamma = (const float*)d_in[2];  // (768,)
    const float* beta  = (const float*)d_in[3];  // (768,)
    const float* w     = (const float*)d_in[4];  // (768,200)
    const float* bc    = (const float*)d_in[5];  // (200,)
    float* out = (float*)d_out;

    const size_t smem1 = (size_t)(TILE_P*ND        // xs
                                + TILE_P*KF        // a_c
                                + TILE_P           // a16
                                + KP1) * sizeof(float);  // ~75.4 KB
    cudaFuncSetAttribute(k1, cudaFuncAttributeMaxDynamicSharedMemorySize, (int)smem1);

    k1<<<dim3(NTILES, NB), T1, smem1>>>(x, proto, out);
    k2a<<<NB*KF, 256>>>(out, gamma, beta, bc);
    k2b<<<dim3(16, NB), 256>>>(w, out);
}

// round 9
// speedup vs baseline: 2.1001x; 2.0155x over previous
#include <cuda_runtime.h>
#include <math_constants.h>

// Problem constants
#define NB 32
#define NP 576
#define ND 768
#define KP1 17
#define KF 16
#define NC 200
#define TILE_P 64
#define NTILES 9      // 576 / 64
#define T1 512

// Output layout: concatenation of (A, v_norm, logits_parts, logits_agg)
#define SZ_A (NB*KP1*NP)            // 313344
#define OFF_VN (SZ_A)
#define SZ_VN (NB*KF*ND)            // 393216
#define OFF_PARTS (OFF_VN + SZ_VN)
#define SZ_PARTS (NB*KF*NC)         // 102400
#define OFF_AGG (OFF_PARTS + SZ_PARTS)

typedef unsigned long long u64;

// v accumulator (pre-LN). Zeroed at module load; k2a re-zeroes after reading,
// so the "g_v == 0 on k1 entry" invariant holds across graph replays.
__device__ float g_v[NB*KF*ND];

// ---- f32x2 helpers (k2b only — measured SLOWER than scalar in k1 loops) ----
__device__ __forceinline__ u64 fma2(u64 a, u64 b, u64 c) {
    u64 d; asm("fma.rn.f32x2 %0, %1, %2, %3;" : "=l"(d) : "l"(a), "l"(b), "l"(c));
    return d;
}
__device__ __forceinline__ u64 pack2(float lo, float hi) {
    u64 r; asm("mov.b64 %0, {%1,%2};" : "=l"(r) : "f"(lo), "f"(hi));
    return r;
}
__device__ __forceinline__ float2 unpack2(u64 v) {
    float2 r; asm("mov.b64 {%0,%1}, %2;" : "=f"(r.x), "=f"(r.y) : "l"(v));
    return r;
}

// ---------------------------------------------------------------------------
// k1: per (image, 64-patch tile) block. 512 threads, 1 block/SM (218 KB smem).
//  Phase 1: scalar float4 dots (4 patches/warp, 17 proto LDGs amortized over
//           4 patches), 3-level shfl reduce -> float4 partials -> softmax.
//  Phase 2: 384 threads own d-pairs (scalar FMA, float4 a-broadcasts);
//           128 threads write A concurrently. Epilogue: 16 float2 atomics.
// ---------------------------------------------------------------------------
__global__ __launch_bounds__(T1, 1)
void k1(const float* __restrict__ x,
        const float* __restrict__ proto,
        float* __restrict__ out)
{
    extern __shared__ float sm[];
    float* xs     = sm;                        // 64*768 floats (196.6 KB)
    float* a_part = xs + TILE_P*ND;            // 64*17*4 partials (17.4 KB)
    float* a_c    = a_part + TILE_P*KP1*4;     // 64*16 compact a (16B-aligned)
    float* a16    = a_c + TILE_P*KF;           // 64 (k=16 attention)
    float* psq    = a16 + TILE_P;              // 17

    const int t = threadIdx.x, warp = t >> 5, lane = t & 31;
    const int tile = blockIdx.x, b = blockIdx.y;

    // --- stage x tile (float4, coalesced): 12288 float4 / 512 thr ---
    float4* xs4 = (float4*)xs;
    const float4* xg = (const float4*)(x + ((size_t)b*NP + (size_t)tile*TILE_P)*ND);
    #pragma unroll
    for (int i = 0; i < 24; i++)
        xs4[t + i*T1] = xg[t + i*T1];

    // --- per-block ||p_k||^2 (overlaps staging; proto L1/L2-resident) ---
    for (int k = warp; k < KP1; k += 16) {     // warp w: k=w; warp 0 also k=16
        const float4* pk = (const float4*)(proto + (size_t)k*ND);
        float s = 0.f;
        #pragma unroll
        for (int i = 0; i < 6; i++) {
            float4 v = __ldg(&pk[lane + 32*i]);
            s += v.x*v.x + v.y*v.y + v.z*v.z + v.w*v.w;
        }
        #pragma unroll
        for (int o = 16; o; o >>= 1) s += __shfl_xor_sync(0xffffffffu, s, o);
        if (lane == 0) psq[k] = s;
    }
    __syncthreads();

    // --- Phase 1: scalar float4 dots, 4 patches per warp ---
    const int p0 = warp * 4;
    float acc[4][KP1];
    #pragma unroll
    for (int p = 0; p < 4; p++)
        #pragma unroll
        for (int k = 0; k < KP1; k++) acc[p][k] = 0.f;

    const float4* pr4 = (const float4*)proto;
    #pragma unroll
    for (int j = 0; j < 6; j++) {
        float4 xv[4];
        #pragma unroll
        for (int p = 0; p < 4; p++) xv[p] = xs4[(p0 + p)*(ND/4) + j*32 + lane];
        #pragma unroll
        for (int k = 0; k < KP1; k++) {
            float4 pv = __ldg(&pr4[k*(ND/4) + j*32 + lane]);
            #pragma unroll
            for (int p = 0; p < 4; p++)
                acc[p][k] += xv[p].x*pv.x + xv[p].y*pv.y
                           + xv[p].z*pv.z + xv[p].w*pv.w;
        }
    }

    // 3-level shfl reduce -> 4 partials per dot, lanes 0-3 store
    #pragma unroll
    for (int p = 0; p < 4; p++)
        #pragma unroll
        for (int k = 0; k < KP1; k++) {
            float v = acc[p][k];
            v += __shfl_xor_sync(0xffffffffu, v, 16);
            v += __shfl_xor_sync(0xffffffffu, v, 8);
            v += __shfl_xor_sync(0xffffffffu, v, 4);
            if (lane < 4) a_part[((p0 + p)*KP1 + k)*4 + lane] = v;
        }
    __syncwarp();

    // --- lane-parallel softmax: softmax_k(2*xp - psq) == softmax(-dists) ---
    const float4* a_part4 = (const float4*)a_part;
    #pragma unroll
    for (int p = 0; p < 4; p++) {
        const int pl = p0 + p;
        float s = -CUDART_INF_F;
        if (lane < KP1) {
            float4 t4 = a_part4[pl*KP1 + lane];
            float dot = (t4.x + t4.y) + (t4.z + t4.w);
            s = fmaf(2.f, dot, -psq[lane]);
        }
        float m = s;
        #pragma unroll
        for (int o = 16; o; o >>= 1) m = fmaxf(m, __shfl_xor_sync(0xffffffffu, m, o));
        float e = (lane < KP1) ? __expf(s - m) : 0.f;
        float ssum = e;
        #pragma unroll
        for (int o = 16; o; o >>= 1) ssum += __shfl_xor_sync(0xffffffffu, ssum, o);
        float av = e * (1.f / ssum);
        if (lane < KF)       a_c[pl*KF + lane] = av;
        else if (lane == KF) a16[pl] = av;
    }
    __syncthreads();

    if (t >= 384) {
        // --- A output on the 128 spare threads: rows contiguous in p ---
        int tt = t - 384;
        #pragma unroll
        for (int i = tt; i < KP1*TILE_P; i += 128) {
            int k = i >> 6, p = i & 63;
            float av = (k < KF) ? a_c[p*KF + k] : a16[p];
            out[((size_t)b*KP1 + k)*NP + (size_t)tile*TILE_P + p] = av;
        }
    } else {
        // --- Phase 2: thread owns d-pair (2t, 2t+1); scalar FMA ---
        float2 vacc[KF];
        #pragma unroll
        for (int k = 0; k < KF; k++) { vacc[k].x = 0.f; vacc[k].y = 0.f; }
        const float2* xs2 = (const float2*)xs;
        const float4* ac4 = (const float4*)a_c;
        #pragma unroll 4
        for (int p = 0; p < TILE_P; p++) {
            float2 xv = xs2[p*(ND/2) + t];
            float4 a0 = ac4[p*4 + 0], a1 = ac4[p*4 + 1];   // broadcast LDS.128
            float4 a2 = ac4[p*4 + 2], a3 = ac4[p*4 + 3];
            const float av[KF] = { a0.x,a0.y,a0.z,a0.w, a1.x,a1.y,a1.z,a1.w,
                                   a2.x,a2.y,a2.z,a2.w, a3.x,a3.y,a3.z,a3.w };
            #pragma unroll
            for (int k = 0; k < KF; k++) {
                vacc[k].x += av[k] * xv.x;
                vacc[k].y += av[k] * xv.y;
            }
        }
        float2* gv2 = (float2*)(g_v + (size_t)b*KF*ND);
        #pragma unroll
        for (int k = 0; k < KF; k++)
            atomicAdd(&gv2[k*(ND/2) + t], vacc[k]);   // red.global.add.v2.f32
    }
}

// ---------------------------------------------------------------------------
// k2a: LayerNorm over D for each (b,k). Applies the /P scaling.
// Re-zeroes g_v (read-then-clear) and seeds parts/agg with the bias so k2b
// can use pure red.global.add.
// ---------------------------------------------------------------------------
__global__ __launch_bounds__(256, 4)
void k2a(float* __restrict__ out,
         const float* __restrict__ gamma, const float* __restrict__ beta,
         const float* __restrict__ b_cls)
{
    const int bk = blockIdx.x;            // b*16 + k
    const int t = threadIdx.x;
    __shared__ float red[16];
    __shared__ float stats[2];
    float* gv = g_v + (size_t)bk*ND;
    const float invP = 1.f / (float)NP;

    float v[3]; float s = 0.f, sq = 0.f;
    #pragma unroll
    for (int i = 0; i < 3; i++) {
        float val = gv[t + i*256] * invP;
        gv[t + i*256] = 0.f;              // re-zero for next replay's k1
        v[i] = val; s += val; sq += val*val;
    }

    // seed logits_parts / logits_agg with the classifier bias
    if (t < NC) {
        float bcv = b_cls[t];
        out[OFF_PARTS + (size_t)bk*NC + t] = bcv;
        if ((bk & 15) == 0) out[OFF_AGG + (size_t)(bk >> 4)*NC + t] = bcv;
    }

    #pragma unroll
    for (int o = 16; o; o >>= 1) {
        s  += __shfl_xor_sync(0xffffffffu, s, o);
        sq += __shfl_xor_sync(0xffffffffu, sq, o);
    }
    if ((t & 31) == 0) { red[t >> 5] = s; red[8 + (t >> 5)] = sq; }
    __syncthreads();
    if (t == 0) {
        float S = 0.f, Q = 0.f;
        #pragma unroll
        for (int w = 0; w < 8; w++) { S += red[w]; Q += red[8 + w]; }
        float mu  = S * (1.f/ND);
        float var = Q * (1.f/ND) - mu*mu;
        stats[0] = mu; stats[1] = rsqrtf(var + 1e-6f);
    }
    __syncthreads();
    const float mu = stats[0], rs = stats[1];
    #pragma unroll
    for (int i = 0; i < 3; i++) {
        int d = t + i*256;
        out[OFF_VN + (size_t)bk*ND + d] = (v[i] - mu) * rs * gamma[d] + beta[d];
    }
}

// ---------------------------------------------------------------------------
// k2b: logits_parts[b,k,c] += vn[b,k,dchunk] @ w[dchunk,c]; agg folded in.
// 16 d-chunks of 48 per image -> 512 blocks; w L2-resident.
// Bias pre-seeded by k2a, so pure red.global.add.
// ---------------------------------------------------------------------------
#define DCH 48
__global__ __launch_bounds__(256, 4)
void k2b(const float* __restrict__ w, float* __restrict__ out)
{
    const int dc = blockIdx.x;            // 0..15
    const int b  = blockIdx.y;
    const int t  = threadIdx.x;
    __shared__ u64 vn_s[KF*(DCH/2)];      // packed d-pairs (3 KB)

    const float* vn = out + OFF_VN + (size_t)b*KF*ND + dc*DCH;
    for (int i = t; i < KF*(DCH/2); i += 256) {
        int k = i / (DCH/2), dp = i - k*(DCH/2);
        float2 v = *(const float2*)&vn[(size_t)k*ND + 2*dp];
        vn_s[i] = pack2(v.x, v.y);
    }
    __syncthreads();

    if (t < NC) {
        const float* wp = w + (size_t)(dc*DCH)*NC + t;   // coalesced in c
        u64 acc[KF];
        #pragma unroll
        for (int k = 0; k < KF; k++) acc[k] = 0ULL;
        #pragma unroll 8
        for (int dp = 0; dp < DCH/2; dp++) {
            float w0 = __ldg(wp + (size_t)(2*dp)*NC);
            float w1 = __ldg(wp + (size_t)(2*dp + 1)*NC);
            u64 wv = pack2(w0, w1);
            #pragma unroll
            for (int k = 0; k < KF; k++)
                acc[k] = fma2(vn_s[k*(DCH/2) + dp], wv, acc[k]);
        }
        float* parts = out + OFF_PARTS + (size_t)b*KF*NC + t;
        float ssum = 0.f;
        #pragma unroll
        for (int k = 0; k < KF; k++) {
            float2 h = unpack2(acc[k]);
            float s = h.x + h.y;
            atomicAdd(parts + (size_t)k*NC, s);
            ssum += s;
        }
        atomicAdd(out + OFF_AGG + b*NC + t, ssum * (1.f/KF));
    }
}

// ---------------------------------------------------------------------------
extern "C" void kernel_launch(void* const* d_in, const int* in_sizes, int n_in,
                              void* d_out, int out_size)
{
    const float* x     = (const float*)d_in[0];  // (32,24,24,768)
    const float* proto = (const float*)d_in[1];  // (17,768)
    const float* gamma = (const float*)d_in[2];  // (768,)
    const float* beta  = (const float*)d_in[3];  // (768,)
    const float* w     = (const float*)d_in[4];  // (768,200)
    const float* bc    = (const float*)d_in[5];  // (200,)
    float* out = (float*)d_out;

    const size_t smem1 = (size_t)(TILE_P*ND          // xs
                                + TILE_P*KP1*4       // a_part
                                + TILE_P*KF          // a_c
                                + TILE_P             // a16
                                + KP1) * sizeof(float);  // ~218.4 KB
    cudaFuncSetAttribute(k1, cudaFuncAttributeMaxDynamicSharedMemorySize, (int)smem1);

    k1<<<dim3(NTILES, NB), T1, smem1>>>(x, proto, out);
    k2a<<<NB*KF, 256>>>(out, gamma, beta, bc);
    k2b<<<dim3(16, NB), 256>>>(w, out);
}

// round 10
// speedup vs baseline: 2.1784x; 1.0373x over previous
#include <cuda_runtime.h>
#include <math_constants.h>

// Problem constants
#define NB 32
#define NP 576
#define ND 768
#define KP1 17
#define KF 16
#define NC 200
#define TILE_P 64
#define NTILES 9      // 576 / 64
#define T1 512

// Output layout: concatenation of (A, v_norm, logits_parts, logits_agg)
#define SZ_A (NB*KP1*NP)            // 313344
#define OFF_VN (SZ_A)
#define SZ_VN (NB*KF*ND)            // 393216
#define OFF_PARTS (OFF_VN + SZ_VN)
#define SZ_PARTS (NB*KF*NC)         // 102400
#define OFF_AGG (OFF_PARTS + SZ_PARTS)

typedef unsigned long long u64;

// v accumulator (pre-LN). Zeroed at module load; k2a re-zeroes after reading,
// so the "g_v == 0 on k1 entry" invariant holds across graph replays.
__device__ float g_v[NB*KF*ND];

// ---- f32x2 helpers (k2b only — measured SLOWER than scalar in k1 loops) ----
__device__ __forceinline__ u64 fma2(u64 a, u64 b, u64 c) {
    u64 d; asm("fma.rn.f32x2 %0, %1, %2, %3;" : "=l"(d) : "l"(a), "l"(b), "l"(c));
    return d;
}
__device__ __forceinline__ u64 pack2(float lo, float hi) {
    u64 r; asm("mov.b64 %0, {%1,%2};" : "=l"(r) : "f"(lo), "f"(hi));
    return r;
}
__device__ __forceinline__ float2 unpack2(u64 v) {
    float2 r; asm("mov.b64 {%0,%1}, %2;" : "=f"(r.x), "=f"(r.y) : "l"(v));
    return r;
}

// ---------------------------------------------------------------------------
// k1: per (image, 64-patch tile) block. 512 threads, 1 block/SM (218 KB smem).
//  Staging pipelined by warp specialization:
//    all threads stage h0 (patches 0-31) -> warps 0-7 compute h0 dots/softmax
//    while warps 8-15 stage h1 alone (named barrier) then compute h1.
//  Phase 2: 384 threads own d-pairs (scalar FMA, float4 a-broadcasts);
//           128 threads write A concurrently. Epilogue: 16 float2 atomics.
// ---------------------------------------------------------------------------
__global__ __launch_bounds__(T1, 1)
void k1(const float* __restrict__ x,
        const float* __restrict__ proto,
        float* __restrict__ out)
{
    extern __shared__ float sm[];
    float* xs     = sm;                        // 64*768 floats (196.6 KB)
    float* a_part = xs + TILE_P*ND;            // 64*17*4 partials (17.4 KB)
    float* a_c    = a_part + TILE_P*KP1*4;     // 64*16 compact a (16B-aligned)
    float* a16    = a_c + TILE_P*KF;           // 64 (k=16 attention)
    float* psq    = a16 + TILE_P;              // 17

    const int t = threadIdx.x, warp = t >> 5, lane = t & 31;
    const int tile = blockIdx.x, b = blockIdx.y;

    float4* xs4 = (float4*)xs;
    const float4* xg = (const float4*)(x + ((size_t)b*NP + (size_t)tile*TILE_P)*ND);

    // --- stage HALF 0 (patches 0-31: 6144 float4) with all 512 threads ---
    #pragma unroll
    for (int i = 0; i < 12; i++)
        xs4[t + i*T1] = xg[t + i*T1];

    // --- per-block ||p_k||^2 (overlaps staging; proto L1/L2-resident) ---
    for (int k = warp; k < KP1; k += 16) {     // warp w: k=w; warp 0 also k=16
        const float4* pk = (const float4*)(proto + (size_t)k*ND);
        float s = 0.f;
        #pragma unroll
        for (int i = 0; i < 6; i++) {
            float4 v = __ldg(&pk[lane + 32*i]);
            s += v.x*v.x + v.y*v.y + v.z*v.z + v.w*v.w;
        }
        #pragma unroll
        for (int o = 16; o; o >>= 1) s += __shfl_xor_sync(0xffffffffu, s, o);
        if (lane == 0) psq[k] = s;
    }
    __syncthreads();    // h0 + psq visible

    // --- warps 8-15: stage HALF 1 (patches 32-63) before their dots ---
    if (warp >= 8) {
        const int tt = t - 256;
        #pragma unroll
        for (int i = 0; i < 24; i++)
            xs4[6144 + tt + i*256] = xg[6144 + tt + i*256];
        asm volatile("bar.sync 1, 256;" ::: "memory");   // warps 8-15 only
    }

    // --- Phase 1: scalar float4 dots, 4 patches per warp.
    //     warps 0-7 -> patches 0-31 (h0, already staged);
    //     warps 8-15 -> patches 32-63 (h1, just staged by them). ---
    const int p0 = warp * 4;
    {
        float acc[4][KP1];
        #pragma unroll
        for (int p = 0; p < 4; p++)
            #pragma unroll
            for (int k = 0; k < KP1; k++) acc[p][k] = 0.f;

        const float4* pr4 = (const float4*)proto;
        #pragma unroll
        for (int j = 0; j < 6; j++) {
            float4 xv[4];
            #pragma unroll
            for (int p = 0; p < 4; p++) xv[p] = xs4[(p0 + p)*(ND/4) + j*32 + lane];
            #pragma unroll
            for (int k = 0; k < KP1; k++) {
                float4 pv = __ldg(&pr4[k*(ND/4) + j*32 + lane]);
                #pragma unroll
                for (int p = 0; p < 4; p++)
                    acc[p][k] += xv[p].x*pv.x + xv[p].y*pv.y
                               + xv[p].z*pv.z + xv[p].w*pv.w;
            }
        }

        // 3-level shfl reduce -> 4 partials per dot, lanes 0-3 store
        #pragma unroll
        for (int p = 0; p < 4; p++)
            #pragma unroll
            for (int k = 0; k < KP1; k++) {
                float v = acc[p][k];
                v += __shfl_xor_sync(0xffffffffu, v, 16);
                v += __shfl_xor_sync(0xffffffffu, v, 8);
                v += __shfl_xor_sync(0xffffffffu, v, 4);
                if (lane < 4) a_part[((p0 + p)*KP1 + k)*4 + lane] = v;
            }
    }
    __syncwarp();

    // --- lane-parallel softmax: softmax_k(2*xp - psq) == softmax(-dists) ---
    const float4* a_part4 = (const float4*)a_part;
    #pragma unroll
    for (int p = 0; p < 4; p++) {
        const int pl = p0 + p;
        float s = -CUDART_INF_F;
        if (lane < KP1) {
            float4 t4 = a_part4[pl*KP1 + lane];
            float dot = (t4.x + t4.y) + (t4.z + t4.w);
            s = fmaf(2.f, dot, -psq[lane]);
        }
        float m = s;
        #pragma unroll
        for (int o = 16; o; o >>= 1) m = fmaxf(m, __shfl_xor_sync(0xffffffffu, m, o));
        float e = (lane < KP1) ? __expf(s - m) : 0.f;
        float ssum = e;
        #pragma unroll
        for (int o = 16; o; o >>= 1) ssum += __shfl_xor_sync(0xffffffffu, ssum, o);
        float av = e * (1.f / ssum);
        if (lane < KF)       a_c[pl*KF + lane] = av;
        else if (lane == KF) a16[pl] = av;
    }
    __syncthreads();

    if (t >= 384) {
        // --- A output on the 128 spare threads: rows contiguous in p ---
        int tt = t - 384;
        #pragma unroll
        for (int i = tt; i < KP1*TILE_P; i += 128) {
            int k = i >> 6, p = i & 63;
            float av = (k < KF) ? a_c[p*KF + k] : a16[p];
            out[((size_t)b*KP1 + k)*NP + (size_t)tile*TILE_P + p] = av;
        }
    } else {
        // --- Phase 2: thread owns d-pair (2t, 2t+1); scalar FMA ---
        float2 vacc[KF];
        #pragma unroll
        for (int k = 0; k < KF; k++) { vacc[k].x = 0.f; vacc[k].y = 0.f; }
        const float2* xs2 = (const float2*)xs;
        const float4* ac4 = (const float4*)a_c;
        #pragma unroll 4
        for (int p = 0; p < TILE_P; p++) {
            float2 xv = xs2[p*(ND/2) + t];
            float4 a0 = ac4[p*4 + 0], a1 = ac4[p*4 + 1];   // broadcast LDS.128
            float4 a2 = ac4[p*4 + 2], a3 = ac4[p*4 + 3];
            const float av[KF] = { a0.x,a0.y,a0.z,a0.w, a1.x,a1.y,a1.z,a1.w,
                                   a2.x,a2.y,a2.z,a2.w, a3.x,a3.y,a3.z,a3.w };
            #pragma unroll
            for (int k = 0; k < KF; k++) {
                vacc[k].x += av[k] * xv.x;
                vacc[k].y += av[k] * xv.y;
            }
        }
        float2* gv2 = (float2*)(g_v + (size_t)b*KF*ND);
        #pragma unroll
        for (int k = 0; k < KF; k++)
            atomicAdd(&gv2[k*(ND/2) + t], vacc[k]);   // red.global.add.v2.f32
    }
}

// ---------------------------------------------------------------------------
// k2a: LayerNorm over D for each (b,k). Applies the /P scaling.
// Re-zeroes g_v (read-then-clear) and seeds parts/agg with the bias so k2b
// can use pure red.global.add.
// ---------------------------------------------------------------------------
__global__ __launch_bounds__(256, 4)
void k2a(float* __restrict__ out,
         const float* __restrict__ gamma, const float* __restrict__ beta,
         const float* __restrict__ b_cls)
{
    const int bk = blockIdx.x;            // b*16 + k
    const int t = threadIdx.x;
    __shared__ float red[16];
    __shared__ float stats[2];
    float* gv = g_v + (size_t)bk*ND;
    const float invP = 1.f / (float)NP;

    float v[3]; float s = 0.f, sq = 0.f;
    #pragma unroll
    for (int i = 0; i < 3; i++) {
        float val = gv[t + i*256] * invP;
        gv[t + i*256] = 0.f;              // re-zero for next replay's k1
        v[i] = val; s += val; sq += val*val;
    }

    // seed logits_parts / logits_agg with the classifier bias
    if (t < NC) {
        float bcv = b_cls[t];
        out[OFF_PARTS + (size_t)bk*NC + t] = bcv;
        if ((bk & 15) == 0) out[OFF_AGG + (size_t)(bk >> 4)*NC + t] = bcv;
    }

    #pragma unroll
    for (int o = 16; o; o >>= 1) {
        s  += __shfl_xor_sync(0xffffffffu, s, o);
        sq += __shfl_xor_sync(0xffffffffu, sq, o);
    }
    if ((t & 31) == 0) { red[t >> 5] = s; red[8 + (t >> 5)] = sq; }
    __syncthreads();
    if (t == 0) {
        float S = 0.f, Q = 0.f;
        #pragma unroll
        for (int w = 0; w < 8; w++) { S += red[w]; Q += red[8 + w]; }
        float mu  = S * (1.f/ND);
        float var = Q * (1.f/ND) - mu*mu;
        stats[0] = mu; stats[1] = rsqrtf(var + 1e-6f);
    }
    __syncthreads();
    const float mu = stats[0], rs = stats[1];
    #pragma unroll
    for (int i = 0; i < 3; i++) {
        int d = t + i*256;
        out[OFF_VN + (size_t)bk*ND + d] = (v[i] - mu) * rs * gamma[d] + beta[d];
    }
}

// ---------------------------------------------------------------------------
// k2b: logits_parts[b,k,c] += vn[b,k,dchunk] @ w[dchunk,c]; agg folded in.
// Grid (16 dc, 32 b, 2 k-halves) = 1024 blocks: each thread handles 8 k's
// over a fully-unrolled 24-iter loop (max MLP). Bias pre-seeded by k2a.
// ---------------------------------------------------------------------------
#define DCH 48
#define KH 8
__global__ __launch_bounds__(256, 4)
void k2b(const float* __restrict__ w, float* __restrict__ out)
{
    const int dc = blockIdx.x;            // 0..15
    const int b  = blockIdx.y;
    const int kh = blockIdx.z;            // 0..1 -> k in [kh*8, kh*8+8)
    const int t  = threadIdx.x;
    __shared__ u64 vn_s[KH*(DCH/2)];      // packed d-pairs (1.5 KB)

    const float* vn = out + OFF_VN + ((size_t)b*KF + kh*KH)*ND + dc*DCH;
    for (int i = t; i < KH*(DCH/2); i += 256) {
        int k = i / (DCH/2), dp = i - k*(DCH/2);
        float2 v = *(const float2*)&vn[(size_t)k*ND + 2*dp];
        vn_s[i] = pack2(v.x, v.y);
    }
    __syncthreads();

    if (t < NC) {
        const float* wp = w + (size_t)(dc*DCH)*NC + t;   // coalesced in c
        u64 acc[KH];
        #pragma unroll
        for (int k = 0; k < KH; k++) acc[k] = 0ULL;
        #pragma unroll
        for (int dp = 0; dp < DCH/2; dp++) {
            float w0 = __ldg(wp + (size_t)(2*dp)*NC);
            float w1 = __ldg(wp + (size_t)(2*dp + 1)*NC);
            u64 wv = pack2(w0, w1);
            #pragma unroll
            for (int k = 0; k < KH; k++)
                acc[k] = fma2(vn_s[k*(DCH/2) + dp], wv, acc[k]);
        }
        float* parts = out + OFF_PARTS + ((size_t)b*KF + kh*KH)*NC + t;
        float ssum = 0.f;
        #pragma unroll
        for (int k = 0; k < KH; k++) {
            float2 h = unpack2(acc[k]);
            float s = h.x + h.y;
            atomicAdd(parts + (size_t)k*NC, s);
            ssum += s;
        }
        atomicAdd(out + OFF_AGG + b*NC + t, ssum * (1.f/KF));
    }
}

// ---------------------------------------------------------------------------
extern "C" void kernel_launch(void* const* d_in, const int* in_sizes, int n_in,
                              void* d_out, int out_size)
{
    const float* x     = (const float*)d_in[0];  // (32,24,24,768)
    const float* proto = (const float*)d_in[1];  // (17,768)
    const float* gamma = (const float*)d_in[2];  // (768,)
    const float* beta  = (const float*)d_in[3];  // (768,)
    const float* w     = (const float*)d_in[4];  // (768,200)
    const float* bc    = (const float*)d_in[5];  // (200,)
    float* out = (float*)d_out;

    const size_t smem1 = (size_t)(TILE_P*ND          // xs
                                + TILE_P*KP1*4       // a_part
                                + TILE_P*KF          // a_c
                                + TILE_P             // a16
                                + KP1) * sizeof(float);  // ~218.4 KB
    cudaFuncSetAttribute(k1, cudaFuncAttributeMaxDynamicSharedMemorySize, (int)smem1);

    k1<<<dim3(NTILES, NB), T1, smem1>>>(x, proto, out);
    k2a<<<NB*KF, 256>>>(out, gamma, beta, bc);
    k2b<<<dim3(16, NB, 2), 256>>>(w, out);
}